// round 4
// baseline (speedup 1.0000x reference)
#include <cuda_runtime.h>
#include <math.h>
#include <float.h>

#define QN 16384
#define VN 4096
#define RPB 16               // rows per block
#define NBLK (QN / RPB)      // 1024 blocks

// Scratch (allocation-free). Zero static init is the correct initial state:
// g_segmax_enc uses an order-preserving uint encoding where 0 == -inf.
__device__ float    g_colsum[VN];
__device__ unsigned g_segmax_enc[VN];
__device__ float    g_segsum[VN];
__device__ float    g_s[QN];
__device__ float    g_t2v;

__device__ __forceinline__ unsigned enc_f(float x) {
    unsigned u = __float_as_uint(x);
    return (u & 0x80000000u) ? ~u : (u | 0x80000000u);
}
__device__ __forceinline__ float dec_f(unsigned u) {
    return (u & 0x80000000u) ? __uint_as_float(u ^ 0x80000000u)
                             : __uint_as_float(~u);
}

// Single fused pass over the 256MB matrix. 2 rows per iteration: 8 LDG.128
// issued back-to-back before first use -> MLP 8/warp, hides DRAM latency.
//  - row sum(exp): warp shuffle reduce, cross-warp combine ONCE at end
//  - column sum(exp): register accumulators (thread owns 16 fixed columns)
//  - segment max of matched scores: atomicMax on order-preserving uint
__global__ __launch_bounds__(256) void main_kernel(
    const float* __restrict__ scores, const int* __restrict__ labels) {
    __shared__ float rowsum[RPB][8];
    __shared__ float s_t2v;

    int t = threadIdx.x;
    int lane = t & 31, warp = t >> 5;
    if (t == 0) s_t2v = 0.f;

    float4 a0 = make_float4(0.f, 0.f, 0.f, 0.f);
    float4 a1 = a0, a2 = a0, a3 = a0;

    int row0 = blockIdx.x * RPB;
    const float4* base = (const float4*)(scores + (size_t)row0 * VN);

    #pragma unroll 1
    for (int r = 0; r < RPB; r += 2) {
        const float4* rpA = base + (size_t)r * (VN / 4);
        const float4* rpB = rpA + (VN / 4);
        // 8 independent 16B loads in flight before any consumption
        float4 vA0 = rpA[t];
        float4 vA1 = rpA[t + 256];
        float4 vA2 = rpA[t + 512];
        float4 vA3 = rpA[t + 768];
        float4 vB0 = rpB[t];
        float4 vB1 = rpB[t + 256];
        float4 vB2 = rpB[t + 512];
        float4 vB3 = rpB[t + 768];

        float e00 = __expf(vA0.x), e01 = __expf(vA0.y), e02 = __expf(vA0.z), e03 = __expf(vA0.w);
        float e10 = __expf(vA1.x), e11 = __expf(vA1.y), e12 = __expf(vA1.z), e13 = __expf(vA1.w);
        float e20 = __expf(vA2.x), e21 = __expf(vA2.y), e22 = __expf(vA2.z), e23 = __expf(vA2.w);
        float e30 = __expf(vA3.x), e31 = __expf(vA3.y), e32 = __expf(vA3.z), e33 = __expf(vA3.w);
        a0.x += e00; a0.y += e01; a0.z += e02; a0.w += e03;
        a1.x += e10; a1.y += e11; a1.z += e12; a1.w += e13;
        a2.x += e20; a2.y += e21; a2.z += e22; a2.w += e23;
        a3.x += e30; a3.y += e31; a3.z += e32; a3.w += e33;
        float pA = ((e00 + e01) + (e02 + e03)) + ((e10 + e11) + (e12 + e13))
                 + ((e20 + e21) + (e22 + e23)) + ((e30 + e31) + (e32 + e33));

        float f00 = __expf(vB0.x), f01 = __expf(vB0.y), f02 = __expf(vB0.z), f03 = __expf(vB0.w);
        float f10 = __expf(vB1.x), f11 = __expf(vB1.y), f12 = __expf(vB1.z), f13 = __expf(vB1.w);
        float f20 = __expf(vB2.x), f21 = __expf(vB2.y), f22 = __expf(vB2.z), f23 = __expf(vB2.w);
        float f30 = __expf(vB3.x), f31 = __expf(vB3.y), f32 = __expf(vB3.z), f33 = __expf(vB3.w);
        a0.x += f00; a0.y += f01; a0.z += f02; a0.w += f03;
        a1.x += f10; a1.y += f11; a1.z += f12; a1.w += f13;
        a2.x += f20; a2.y += f21; a2.z += f22; a2.w += f23;
        a3.x += f30; a3.y += f31; a3.z += f32; a3.w += f33;
        float pB = ((f00 + f01) + (f02 + f03)) + ((f10 + f11) + (f12 + f13))
                 + ((f20 + f21) + (f22 + f23)) + ((f30 + f31) + (f32 + f33));

        #pragma unroll
        for (int o = 16; o > 0; o >>= 1) {
            pA += __shfl_xor_sync(0xffffffffu, pA, o);
            pB += __shfl_xor_sync(0xffffffffu, pB, o);
        }
        if (lane == 0) {
            rowsum[r][warp] = pA;
            rowsum[r + 1][warp] = pB;
        }
    }
    __syncthreads();

    if (t < RPB) {
        int row = row0 + t;
        float sum = rowsum[t][0];
        #pragma unroll
        for (int w = 1; w < 8; w++) sum += rowsum[t][w];
        int lab = labels[row] & (VN - 1);
        float s = __ldg(scores + (size_t)row * VN + lab);
        g_s[row] = s;
        atomicMax(&g_segmax_enc[lab], enc_f(s));
        atomicAdd(&s_t2v, __logf(sum) - s);
    }
    __syncthreads();
    if (t == 0) atomicAdd(&g_t2v, s_t2v);

    // flush register column partials (4096 atomics/block)
    atomicAdd(&g_colsum[4 * t + 0], a0.x);
    atomicAdd(&g_colsum[4 * t + 1], a0.y);
    atomicAdd(&g_colsum[4 * t + 2], a0.z);
    atomicAdd(&g_colsum[4 * t + 3], a0.w);
    atomicAdd(&g_colsum[4 * (t + 256) + 0], a1.x);
    atomicAdd(&g_colsum[4 * (t + 256) + 1], a1.y);
    atomicAdd(&g_colsum[4 * (t + 256) + 2], a1.z);
    atomicAdd(&g_colsum[4 * (t + 256) + 3], a1.w);
    atomicAdd(&g_colsum[4 * (t + 512) + 0], a2.x);
    atomicAdd(&g_colsum[4 * (t + 512) + 1], a2.y);
    atomicAdd(&g_colsum[4 * (t + 512) + 2], a2.z);
    atomicAdd(&g_colsum[4 * (t + 512) + 3], a2.w);
    atomicAdd(&g_colsum[4 * (t + 768) + 0], a3.x);
    atomicAdd(&g_colsum[4 * (t + 768) + 1], a3.y);
    atomicAdd(&g_colsum[4 * (t + 768) + 2], a3.z);
    atomicAdd(&g_colsum[4 * (t + 768) + 3], a3.w);
}

// Segmented sum spread across the chip (global atomics, ~4 adds/segment)
__global__ void segsum_kernel(const int* __restrict__ labels) {
    int q = blockIdx.x * blockDim.x + threadIdx.x;
    if (q >= QN) return;
    int lab = labels[q] & (VN - 1);
    float m = dec_f(g_segmax_enc[lab]);
    atomicAdd(&g_segsum[lab], __expf(g_s[q] - m));
}

// Single block: v-loop + output + scratch reset for the next graph replay.
__global__ __launch_bounds__(1024) void final_kernel(float* __restrict__ out) {
    __shared__ float warpsum[32];
    int t = threadIdx.x;
    float acc = 0.f;
    #pragma unroll
    for (int v = t; v < VN; v += 1024) {
        float m = dec_f(g_segmax_enc[v]);
        float nom = m + __logf(g_segsum[v]);      // v2t nominator
        acc += __logf(g_colsum[v]) - nom;         // (denominator - nominator)
    }
    #pragma unroll
    for (int o = 16; o > 0; o >>= 1)
        acc += __shfl_xor_sync(0xffffffffu, acc, o);
    if ((t & 31) == 0) warpsum[t >> 5] = acc;
    __syncthreads();
    if (t == 0) {
        float sum = 0.f;
        #pragma unroll
        for (int w = 0; w < 32; w++) sum += warpsum[w];
        out[0] = g_t2v / (float)QN + sum / (float)VN;
    }
    __syncthreads();   // all reads of scratch complete before reset
    #pragma unroll
    for (int v = t; v < VN; v += 1024) {
        g_colsum[v] = 0.f;
        g_segsum[v] = 0.f;
        g_segmax_enc[v] = 0u;
    }
    if (t == 0) g_t2v = 0.f;
}

extern "C" void kernel_launch(void* const* d_in, const int* in_sizes, int n_in,
                              void* d_out, int out_size) {
    const float* scores = (const float*)d_in[0];
    const int* labels = (const int*)d_in[1];
    float* out = (float*)d_out;

    main_kernel<<<NBLK, 256>>>(scores, labels);
    segsum_kernel<<<(QN + 255) / 256, 256>>>(labels);
    final_kernel<<<1, 1024>>>(out);
}

// round 5
// speedup vs baseline: 1.2570x; 1.2570x over previous
#include <cuda_runtime.h>
#include <math.h>
#include <float.h>

#define QN 16384
#define VN 4096
#define RPB 32               // rows per block
#define NBLK (QN / RPB)      // 512 blocks

// Scratch (allocation-free). Zero static init is the correct initial state:
// g_segmax_enc uses an order-preserving uint encoding where 0 == -inf.
__device__ float    g_colsum[VN];
__device__ unsigned g_segmax_enc[VN];
__device__ float    g_segsum[VN];
__device__ float    g_s[QN];
__device__ float    g_t2v;

__device__ __forceinline__ unsigned enc_f(float x) {
    unsigned u = __float_as_uint(x);
    return (u & 0x80000000u) ? ~u : (u | 0x80000000u);
}
__device__ __forceinline__ float dec_f(unsigned u) {
    return (u & 0x80000000u) ? __uint_as_float(u ^ 0x80000000u)
                             : __uint_as_float(~u);
}

// Single fused pass over the 256MB matrix. No barriers in the hot loop;
// no unroll pragma — ptxas unrolls and front-batches the LDGs itself.
//  - row sum(exp): warp shuffle reduce per row, cross-warp combine ONCE at end
//  - column sum(exp): register accumulators (thread owns 16 fixed columns)
//  - segment max of matched scores: atomicMax on order-preserving uint
__global__ __launch_bounds__(256) void main_kernel(
    const float* __restrict__ scores, const int* __restrict__ labels) {
    __shared__ float rowsum[RPB][8];
    __shared__ float s_t2v;

    int t = threadIdx.x;
    int lane = t & 31, warp = t >> 5;
    if (t == 0) s_t2v = 0.f;

    float4 a0 = make_float4(0.f, 0.f, 0.f, 0.f);
    float4 a1 = a0, a2 = a0, a3 = a0;

    int row0 = blockIdx.x * RPB;
    const float4* base = (const float4*)(scores + (size_t)row0 * VN);

    for (int r = 0; r < RPB; r++) {
        const float4* rp = base + (size_t)r * (VN / 4);
        float4 v0 = __ldcs(rp + t);
        float4 v1 = __ldcs(rp + t + 256);
        float4 v2 = __ldcs(rp + t + 512);
        float4 v3 = __ldcs(rp + t + 768);

        float e00 = __expf(v0.x), e01 = __expf(v0.y), e02 = __expf(v0.z), e03 = __expf(v0.w);
        float e10 = __expf(v1.x), e11 = __expf(v1.y), e12 = __expf(v1.z), e13 = __expf(v1.w);
        float e20 = __expf(v2.x), e21 = __expf(v2.y), e22 = __expf(v2.z), e23 = __expf(v2.w);
        float e30 = __expf(v3.x), e31 = __expf(v3.y), e32 = __expf(v3.z), e33 = __expf(v3.w);

        a0.x += e00; a0.y += e01; a0.z += e02; a0.w += e03;
        a1.x += e10; a1.y += e11; a1.z += e12; a1.w += e13;
        a2.x += e20; a2.y += e21; a2.z += e22; a2.w += e23;
        a3.x += e30; a3.y += e31; a3.z += e32; a3.w += e33;

        float p = ((e00 + e01) + (e02 + e03)) + ((e10 + e11) + (e12 + e13))
                + ((e20 + e21) + (e22 + e23)) + ((e30 + e31) + (e32 + e33));
        #pragma unroll
        for (int o = 16; o > 0; o >>= 1)
            p += __shfl_xor_sync(0xffffffffu, p, o);
        if (lane == 0) rowsum[r][warp] = p;
    }
    __syncthreads();

    if (t < RPB) {
        int row = row0 + t;
        float sum = rowsum[t][0];
        #pragma unroll
        for (int w = 1; w < 8; w++) sum += rowsum[t][w];
        int lab = labels[row] & (VN - 1);
        float s = __ldg(scores + (size_t)row * VN + lab);
        g_s[row] = s;
        atomicMax(&g_segmax_enc[lab], enc_f(s));
        atomicAdd(&s_t2v, __logf(sum) - s);
    }
    __syncthreads();
    if (t == 0) atomicAdd(&g_t2v, s_t2v);

    // flush register column partials (4096 atomics/block; 2M total)
    atomicAdd(&g_colsum[4 * t + 0], a0.x);
    atomicAdd(&g_colsum[4 * t + 1], a0.y);
    atomicAdd(&g_colsum[4 * t + 2], a0.z);
    atomicAdd(&g_colsum[4 * t + 3], a0.w);
    atomicAdd(&g_colsum[4 * (t + 256) + 0], a1.x);
    atomicAdd(&g_colsum[4 * (t + 256) + 1], a1.y);
    atomicAdd(&g_colsum[4 * (t + 256) + 2], a1.z);
    atomicAdd(&g_colsum[4 * (t + 256) + 3], a1.w);
    atomicAdd(&g_colsum[4 * (t + 512) + 0], a2.x);
    atomicAdd(&g_colsum[4 * (t + 512) + 1], a2.y);
    atomicAdd(&g_colsum[4 * (t + 512) + 2], a2.z);
    atomicAdd(&g_colsum[4 * (t + 512) + 3], a2.w);
    atomicAdd(&g_colsum[4 * (t + 768) + 0], a3.x);
    atomicAdd(&g_colsum[4 * (t + 768) + 1], a3.y);
    atomicAdd(&g_colsum[4 * (t + 768) + 2], a3.z);
    atomicAdd(&g_colsum[4 * (t + 768) + 3], a3.w);
}

// Segmented sum spread across the chip (global atomics, ~4 adds/segment)
__global__ void segsum_kernel(const int* __restrict__ labels) {
    int q = blockIdx.x * blockDim.x + threadIdx.x;
    if (q >= QN) return;
    int lab = labels[q] & (VN - 1);
    float m = dec_f(g_segmax_enc[lab]);
    atomicAdd(&g_segsum[lab], __expf(g_s[q] - m));
}

// Single block: v-loop + output + scratch reset for the next graph replay.
__global__ __launch_bounds__(1024) void final_kernel(float* __restrict__ out) {
    __shared__ float warpsum[32];
    int t = threadIdx.x;
    float acc = 0.f;
    #pragma unroll
    for (int v = t; v < VN; v += 1024) {
        float m = dec_f(g_segmax_enc[v]);
        float nom = m + __logf(g_segsum[v]);      // v2t nominator
        acc += __logf(g_colsum[v]) - nom;         // (denominator - nominator)
    }
    #pragma unroll
    for (int o = 16; o > 0; o >>= 1)
        acc += __shfl_xor_sync(0xffffffffu, acc, o);
    if ((t & 31) == 0) warpsum[t >> 5] = acc;
    __syncthreads();
    if (t == 0) {
        float sum = 0.f;
        #pragma unroll
        for (int w = 0; w < 32; w++) sum += warpsum[w];
        out[0] = g_t2v / (float)QN + sum / (float)VN;
    }
    __syncthreads();   // all reads of scratch complete before reset
    #pragma unroll
    for (int v = t; v < VN; v += 1024) {
        g_colsum[v] = 0.f;
        g_segsum[v] = 0.f;
        g_segmax_enc[v] = 0u;
    }
    if (t == 0) g_t2v = 0.f;
}

extern "C" void kernel_launch(void* const* d_in, const int* in_sizes, int n_in,
                              void* d_out, int out_size) {
    const float* scores = (const float*)d_in[0];
    const int* labels = (const int*)d_in[1];
    float* out = (float*)d_out;

    main_kernel<<<NBLK, 256>>>(scores, labels);
    segsum_kernel<<<(QN + 255) / 256, 256>>>(labels);
    final_kernel<<<1, 1024>>>(out);
}